// round 1
// baseline (speedup 1.0000x reference)
#include <cuda_runtime.h>
#include <cuda_fp16.h>
#include <cstdint>

#define B_   64
#define T_   512
#define H_   128
#define E_   300
#define C_   20
#define G4_  512
#define BT_  (B_ * T_)          // 32768

// -------- scratch (static device globals; no runtime allocation) -----------
__device__ __align__(16) float g_xw[2u * BT_ * G4_];   // 128 MB: [dir][bt][512]
__device__ __align__(16) float g_h [(unsigned)BT_ * 2 * H_];    // 32 MB: [bt][256] (hf|hb)
__device__ float g_res[B_];

// ----------------------------- math helpers --------------------------------
__device__ __forceinline__ float fast_sigmoid(float x) {
    return __fdividef(1.0f, 1.0f + __expf(-x));
}
__device__ __forceinline__ float fast_tanh(float x) {
    float ax = fabsf(x);
    float e  = __expf(-2.0f * ax);
    float t  = __fdividef(1.0f - e, 1.0f + e);
    return copysignf(t, x);
}
__device__ __forceinline__ int load_mask(const void* m, long idx, int isbyte) {
    return isbyte ? (int)((const unsigned char*)m)[idx] : ((const int*)m)[idx];
}

// ==========================================================================
// Kernel 1: fused embedding gather + input GEMM (both directions)
//   out[dir][bt][g] = sum_e emb[x[bt]][e] * W_ih[g][e] + b_ih[g] + b_hh[g]
//   M=32768 (bt), N=1024 (dir*512+g), K=300.  BM=128 BN=128 BK=16, 8x8/thread
// ==========================================================================
__global__ void __launch_bounds__(256) k_input_gemm(
    const int*   __restrict__ x,
    const float* __restrict__ emb,
    const float* __restrict__ Wf,  const float* __restrict__ Wb,
    const float* __restrict__ bif, const float* __restrict__ bhf,
    const float* __restrict__ bib, const float* __restrict__ bhb)
{
    __shared__ __align__(16) float sA[16][128];
    __shared__ __align__(16) float sB[16][128];
    __shared__ int sIdx[128];

    const int tid   = threadIdx.x;
    const int m0    = blockIdx.y * 128;
    const int n0    = blockIdx.x * 128;
    const int dir   = n0 >> 9;
    const int gbase = n0 & 511;
    const float* W  = dir ? Wb : Wf;

    if (tid < 128) sIdx[tid] = x[m0 + tid];
    __syncthreads();

    float acc[8][8];
#pragma unroll
    for (int i = 0; i < 8; i++)
#pragma unroll
        for (int j = 0; j < 8; j++) acc[i][j] = 0.0f;

    const int tm0 = (tid >> 4) << 3;
    const int tn0 = (tid & 15) << 3;

    for (int ks = 0; ks < 19; ks++) {
        const int k0 = ks * 16;
        float4 va[2], vb[2];
#pragma unroll
        for (int r = 0; r < 2; r++) {
            int lid = tid * 2 + r;
            int row = lid >> 2;
            int q   = lid & 3;
            int kg  = k0 + 4 * q;
            if (kg < 300) {
                va[r] = *(const float4*)(emb + (long)sIdx[row] * 300 + kg);
                vb[r] = *(const float4*)(W   + (long)(gbase + row) * 300 + kg);
            } else {
                va[r] = make_float4(0.f, 0.f, 0.f, 0.f);
                vb[r] = make_float4(0.f, 0.f, 0.f, 0.f);
            }
        }
        __syncthreads();
#pragma unroll
        for (int r = 0; r < 2; r++) {
            int lid = tid * 2 + r;
            int row = lid >> 2;
            int q   = lid & 3;
            sA[4*q+0][row] = va[r].x; sA[4*q+1][row] = va[r].y;
            sA[4*q+2][row] = va[r].z; sA[4*q+3][row] = va[r].w;
            sB[4*q+0][row] = vb[r].x; sB[4*q+1][row] = vb[r].y;
            sB[4*q+2][row] = vb[r].z; sB[4*q+3][row] = vb[r].w;
        }
        __syncthreads();
#pragma unroll
        for (int kk = 0; kk < 16; kk++) {
            float a[8], b[8];
            *(float4*)(a)     = *(const float4*)&sA[kk][tm0];
            *(float4*)(a + 4) = *(const float4*)&sA[kk][tm0 + 4];
            *(float4*)(b)     = *(const float4*)&sB[kk][tn0];
            *(float4*)(b + 4) = *(const float4*)&sB[kk][tn0 + 4];
#pragma unroll
            for (int i = 0; i < 8; i++)
#pragma unroll
                for (int j = 0; j < 8; j++)
                    acc[i][j] = fmaf(a[i], b[j], acc[i][j]);
        }
    }

    const float* bi = dir ? bib : bif;
    const float* bh = dir ? bhb : bhf;
    float bias[8];
#pragma unroll
    for (int j = 0; j < 8; j++) {
        int g = gbase + tn0 + j;
        bias[j] = bi[g] + bh[g];
    }
    float* outbase = g_xw + (long)dir * BT_ * G4_;
#pragma unroll
    for (int i = 0; i < 8; i++) {
        long rowoff = (long)(m0 + tm0 + i) * G4_ + gbase + tn0;
        float4 o0 = make_float4(acc[i][0] + bias[0], acc[i][1] + bias[1],
                                acc[i][2] + bias[2], acc[i][3] + bias[3]);
        float4 o1 = make_float4(acc[i][4] + bias[4], acc[i][5] + bias[5],
                                acc[i][6] + bias[6], acc[i][7] + bias[7]);
        *(float4*)(outbase + rowoff)     = o0;
        *(float4*)(outbase + rowoff + 4) = o1;
    }
}

// ==========================================================================
// Kernel 2: LSTM recurrence. 128 CTAs = (dir, batch). W_hh resident in smem
// as fp16 with 514-halfword padded rows (conflict-free fill + matvec).
// 256 threads: each owns 2 gates; threads<128 own the hidden/cell update.
// ==========================================================================
__global__ void __launch_bounds__(256) k_lstm(
    const float* __restrict__ Whf, const float* __restrict__ Whb)
{
    extern __shared__ __align__(16) char smem[];
    __half* sW = (__half*)smem;                        // [128][514] halves
    float*  sh = (float*)(smem + 128 * 514 * 2);       // h[128]
    float*  sg = sh + 128;                             // gates[512]

    const int tid = threadIdx.x;
    const int dir = blockIdx.x >> 6;
    const int b   = blockIdx.x & 63;
    const float* Wh = dir ? Whb : Whf;

    // W_hh[g][k] -> sW[k][g] (fp16). Global coalesced over k; smem stride
    // 514 halves => bank advances by 1 per k: conflict-free.
    for (int i = tid; i < G4_ * H_; i += 256) {
        int g = i >> 7, k = i & 127;
        sW[k * 514 + g] = __float2half(Wh[i]);
    }
    if (tid < 128) sh[tid] = 0.0f;
    float c = 0.0f;
    __syncthreads();

    const __half2* sW2 = (const __half2*)sW;           // row stride 257 half2
    const float* xwp = g_xw + (long)dir * BT_ * G4_ + (long)b * T_ * G4_;
    float* hout = g_h + (long)b * T_ * (2 * H_) + (dir ? H_ : 0);

    int t  = dir ? (T_ - 1) : 0;
    const int dt = dir ? -1 : 1;
    const int sec = tid >> 6;   // 0:i 1:f 2:g(tanh) 3:o

    for (int s = 0; s < T_; s++, t += dt) {
        float2 accv = *(const float2*)(xwp + (long)t * G4_ + 2 * tid);
#pragma unroll 16
        for (int k = 0; k < 128; k++) {
            float  hk = sh[k];
            float2 w  = __half22float2(sW2[k * 257 + tid]);
            accv.x = fmaf(w.x, hk, accv.x);
            accv.y = fmaf(w.y, hk, accv.y);
        }
        if (sec == 2) { accv.x = fast_tanh(accv.x);    accv.y = fast_tanh(accv.y); }
        else          { accv.x = fast_sigmoid(accv.x); accv.y = fast_sigmoid(accv.y); }
        *(float2*)(sg + 2 * tid) = accv;
        __syncthreads();
        if (tid < 128) {
            float cc = fmaf(sg[128 + tid], c, sg[tid] * sg[256 + tid]);
            c = cc;
            float hv = sg[384 + tid] * fast_tanh(cc);
            sh[tid] = hv;
            hout[(long)t * (2 * H_) + tid] = hv;
        }
        __syncthreads();
    }
}

// ==========================================================================
// Kernel 3: logits = [h_f|h_b] @ fc_W^T + fc_b.   16 tokens / block.
// ==========================================================================
__global__ void __launch_bounds__(256) k_logits(
    const float* __restrict__ fcW, const float* __restrict__ fcb,
    float* __restrict__ logits)
{
    __shared__ float sW[20 * 257];
    __shared__ float shh[16 * 257];
    const int tid = threadIdx.x;
    const long bt0 = (long)blockIdx.x * 16;

    for (int i = tid; i < 20 * 256; i += 256) {
        int cc = i >> 8, k = i & 255;
        sW[cc * 257 + k] = fcW[i];
    }
    for (int i = tid; i < 16 * 256; i += 256) {
        int tk = i >> 8, k = i & 255;
        shh[tk * 257 + k] = g_h[(bt0 + tk) * 256 + k];
    }
    __syncthreads();
    for (int o = tid; o < 16 * 20; o += 256) {
        int tk = o / 20, cc = o % 20;
        float acc = fcb[cc];
        const float* hr = shh + tk * 257;
        const float* wr = sW  + cc * 257;
#pragma unroll 8
        for (int k = 0; k < 256; k++) acc = fmaf(hr[k], wr[k], acc);
        logits[(bt0 + tk) * C_ + cc] = acc;
    }
}

// ==========================================================================
// Kernel 4: CRF forward scan + log_num, one warp per batch.
// ==========================================================================
__global__ void k_crf(const float* __restrict__ logits,
                      const int*   __restrict__ tags,
                      const void*  __restrict__ maskp,
                      const float* __restrict__ trans)
{
    __shared__ float sT[400];
    __shared__ float sAl[20];
    const int lane = threadIdx.x;
    const int b    = blockIdx.x;
    // mask dtype detection: byte-bool => first 4 bytes are 1,1,1,1
    const int isbyte = (((const int*)maskp)[0] == 0x01010101);

    for (int i = lane; i < 400; i += 32) sT[i] = trans[i];
    __syncwarp();

    float Tc[20];
#pragma unroll
    for (int i = 0; i < 20; i++)
        Tc[i] = (lane < 20) ? sT[i * 20 + lane] : 0.0f;

    const float* lg  = logits + (long)b * T_ * C_;
    const long mbase = (long)b * T_;

    if (lane < 20) sAl[lane] = lg[lane];        // t = 0
    __syncwarp();
    float em = (lane < 20) ? lg[C_ + lane] : 0.0f;

    for (int t = 1; t < T_; t++) {
        float emNext = (t + 1 < T_ && lane < 20) ? lg[(t + 1) * C_ + lane] : 0.0f;
        int   mt = load_mask(maskp, mbase + t, isbyte);
        float v[20];
#pragma unroll
        for (int i = 0; i < 20; i++) v[i] = sAl[i] + Tc[i];
        float mx = v[0];
#pragma unroll
        for (int i = 1; i < 20; i++) mx = fmaxf(mx, v[i]);
        float s = 0.0f;
#pragma unroll
        for (int i = 0; i < 20; i++) s += __expf(v[i] - mx);
        float la   = em + mx + __logf(s);
        float aold = (lane < 20) ? sAl[lane] : 0.0f;
        float anew = mt ? la : aold;
        __syncwarp();
        if (lane < 20) sAl[lane] = anew;
        __syncwarp();
        em = emNext;
    }

    // log_den = logsumexp(final alpha)
    float v  = (lane < 20) ? sAl[lane] : -1e30f;
    float mx = v;
    for (int o = 16; o; o >>= 1) mx = fmaxf(mx, __shfl_xor_sync(0xffffffffu, mx, o));
    float e = (lane < 20) ? __expf(v - mx) : 0.0f;
    for (int o = 16; o; o >>= 1) e += __shfl_xor_sync(0xffffffffu, e, o);
    float log_den = mx + __logf(e);

    // log_num
    float s1 = 0.0f;
    for (int t = lane; t < T_; t += 32) {
        int tg = tags[mbase + t];
        if (load_mask(maskp, mbase + t, isbyte)) s1 += lg[t * C_ + tg];
    }
    for (int t = lane; t < T_ - 1; t += 32) {
        int a = tags[mbase + t], d = tags[mbase + t + 1];
        if (load_mask(maskp, mbase + t, isbyte) &
            load_mask(maskp, mbase + t + 1, isbyte))
            s1 += sT[a * 20 + d];
    }
    for (int o = 16; o; o >>= 1) s1 += __shfl_xor_sync(0xffffffffu, s1, o);
    if (lane == 0) g_res[b] = log_den - s1;
}

// Kernel 5: deterministic mean over batches -> loss
__global__ void k_final(float* __restrict__ out)
{
    const int lane = threadIdx.x;           // 32
    float v = g_res[lane] + g_res[lane + 32];
    for (int o = 16; o; o >>= 1) v += __shfl_xor_sync(0xffffffffu, v, o);
    if (lane == 0) out[0] = v * (1.0f / 64.0f);
}

// ==========================================================================
extern "C" void kernel_launch(void* const* d_in, const int* in_sizes, int n_in,
                              void* d_out, int out_size)
{
    const int*   x      = (const int*)  d_in[0];
    const void*  mask   =               d_in[1];
    const int*   tags   = (const int*)  d_in[2];
    const float* emb    = (const float*)d_in[3];
    const float* W_ih_f = (const float*)d_in[4];
    const float* W_hh_f = (const float*)d_in[5];
    const float* b_ih_f = (const float*)d_in[6];
    const float* b_hh_f = (const float*)d_in[7];
    const float* W_ih_b = (const float*)d_in[8];
    const float* W_hh_b = (const float*)d_in[9];
    const float* b_ih_b = (const float*)d_in[10];
    const float* b_hh_b = (const float*)d_in[11];
    const float* fc_W   = (const float*)d_in[12];
    const float* fc_b   = (const float*)d_in[13];
    const float* trans  = (const float*)d_in[14];

    float* out        = (float*)d_out;
    float* loss_ptr   = out;
    float* logits_ptr = out + 1;          // tuple order: (loss, logits)
    if (out_size == BT_ * C_) {           // logits-only layout fallback
        logits_ptr = out;
        loss_ptr   = nullptr;
    }

    const int lstm_smem = 128 * 514 * 2 + 128 * 4 + 512 * 4;   // 134144 B
    cudaFuncSetAttribute(k_lstm, cudaFuncAttributeMaxDynamicSharedMemorySize,
                         lstm_smem);

    k_input_gemm<<<dim3(8, 256), 256>>>(x, emb, W_ih_f, W_ih_b,
                                        b_ih_f, b_hh_f, b_ih_b, b_hh_b);
    k_lstm<<<128, 256, lstm_smem>>>(W_hh_f, W_hh_b);
    k_logits<<<BT_ / 16, 256>>>(fc_W, fc_b, logits_ptr);
    k_crf<<<B_, 32>>>(logits_ptr, tags, mask, trans);
    if (loss_ptr) k_final<<<1, 32>>>(loss_ptr);
}

// round 2
// speedup vs baseline: 1.1192x; 1.1192x over previous
#include <cuda_runtime.h>
#include <cuda_fp16.h>
#include <cstdint>

#define B_   64
#define T_   512
#define H_   128
#define E_   300
#define C_   20
#define G4_  512
#define BT_  (B_ * T_)          // 32768

// -------- scratch (static device globals; no runtime allocation) -----------
__device__ __align__(16) float g_xw[2u * BT_ * G4_];   // 128 MB: [dir][bt][512]
__device__ __align__(16) float g_h [(unsigned)BT_ * 2 * H_];  // 32 MB
__device__ float g_res[B_];

// ----------------------------- math helpers --------------------------------
__device__ __forceinline__ float fast_sigmoid(float x) {
    return __fdividef(1.0f, 1.0f + __expf(-x));
}
__device__ __forceinline__ float fast_tanh(float x) {
    float ax = fabsf(x);
    float e  = __expf(-2.0f * ax);
    float t  = __fdividef(1.0f - e, 1.0f + e);
    return copysignf(t, x);
}
__device__ __forceinline__ int load_mask(const void* m, long idx, int isbyte) {
    return isbyte ? (int)((const unsigned char*)m)[idx] : ((const int*)m)[idx];
}
// Packed fp32x2 FMA (Blackwell): 2 fp32 FMAs per issue slot. ptxas only emits
// FFMA2 from explicit PTX.
__device__ __forceinline__ float2 ffma2(float2 a, float2 b, float2 c) {
    unsigned long long ua = *reinterpret_cast<unsigned long long*>(&a);
    unsigned long long ub = *reinterpret_cast<unsigned long long*>(&b);
    unsigned long long uc = *reinterpret_cast<unsigned long long*>(&c);
    unsigned long long ud;
    asm("fma.rn.f32x2 %0, %1, %2, %3;" : "=l"(ud) : "l"(ua), "l"(ub), "l"(uc));
    return *reinterpret_cast<float2*>(&ud);
}

// ==========================================================================
// Kernel 1: fused embedding gather + input GEMM (both directions)
//   M=32768 (bt), N=1024 (dir*512+g), K=300.  BM=128 BN=128 BK=16, 8x8/thread
//   Inner product uses FFMA2 (f32x2): 32 packed FMAs per k-slice.
// ==========================================================================
__global__ void __launch_bounds__(256) k_input_gemm(
    const int*   __restrict__ x,
    const float* __restrict__ emb,
    const float* __restrict__ Wf,  const float* __restrict__ Wb,
    const float* __restrict__ bif, const float* __restrict__ bhf,
    const float* __restrict__ bib, const float* __restrict__ bhb)
{
    __shared__ __align__(16) float sA[16][128];
    __shared__ __align__(16) float sB[16][128];
    __shared__ int sIdx[128];

    const int tid   = threadIdx.x;
    const int m0    = blockIdx.y * 128;
    const int n0    = blockIdx.x * 128;
    const int dir   = n0 >> 9;
    const int gbase = n0 & 511;
    const float* W  = dir ? Wb : Wf;

    if (tid < 128) sIdx[tid] = x[m0 + tid];
    __syncthreads();

    float2 acc[8][4];
#pragma unroll
    for (int i = 0; i < 8; i++)
#pragma unroll
        for (int j = 0; j < 4; j++) acc[i][j] = make_float2(0.f, 0.f);

    const int tm0 = (tid >> 4) << 3;
    const int tn0 = (tid & 15) << 3;

    for (int ks = 0; ks < 19; ks++) {
        const int k0 = ks * 16;
        float4 va[2], vb[2];
#pragma unroll
        for (int r = 0; r < 2; r++) {
            int lid = tid * 2 + r;
            int row = lid >> 2;
            int q   = lid & 3;
            int kg  = k0 + 4 * q;
            if (kg < 300) {
                va[r] = *(const float4*)(emb + (long)sIdx[row] * 300 + kg);
                vb[r] = *(const float4*)(W   + (long)(gbase + row) * 300 + kg);
            } else {
                va[r] = make_float4(0.f, 0.f, 0.f, 0.f);
                vb[r] = make_float4(0.f, 0.f, 0.f, 0.f);
            }
        }
        __syncthreads();
#pragma unroll
        for (int r = 0; r < 2; r++) {
            int lid = tid * 2 + r;
            int row = lid >> 2;
            int q   = lid & 3;
            sA[4*q+0][row] = va[r].x; sA[4*q+1][row] = va[r].y;
            sA[4*q+2][row] = va[r].z; sA[4*q+3][row] = va[r].w;
            sB[4*q+0][row] = vb[r].x; sB[4*q+1][row] = vb[r].y;
            sB[4*q+2][row] = vb[r].z; sB[4*q+3][row] = vb[r].w;
        }
        __syncthreads();
#pragma unroll
        for (int kk = 0; kk < 16; kk++) {
            float a[8];
            float2 b2[4];
            *(float4*)(a)     = *(const float4*)&sA[kk][tm0];
            *(float4*)(a + 4) = *(const float4*)&sA[kk][tm0 + 4];
            *(float2*)(&b2[0]) = *(const float2*)&sB[kk][tn0];
            *(float2*)(&b2[1]) = *(const float2*)&sB[kk][tn0 + 2];
            *(float2*)(&b2[2]) = *(const float2*)&sB[kk][tn0 + 4];
            *(float2*)(&b2[3]) = *(const float2*)&sB[kk][tn0 + 6];
#pragma unroll
            for (int i = 0; i < 8; i++) {
                float2 ai = make_float2(a[i], a[i]);
#pragma unroll
                for (int j = 0; j < 4; j++)
                    acc[i][j] = ffma2(ai, b2[j], acc[i][j]);
            }
        }
    }

    const float* bi = dir ? bib : bif;
    const float* bh = dir ? bhb : bhf;
    float bias[8];
#pragma unroll
    for (int j = 0; j < 8; j++) {
        int g = gbase + tn0 + j;
        bias[j] = bi[g] + bh[g];
    }
    float* outbase = g_xw + (long)dir * BT_ * G4_;
#pragma unroll
    for (int i = 0; i < 8; i++) {
        long rowoff = (long)(m0 + tm0 + i) * G4_ + gbase + tn0;
        float4 o0 = make_float4(acc[i][0].x + bias[0], acc[i][0].y + bias[1],
                                acc[i][1].x + bias[2], acc[i][1].y + bias[3]);
        float4 o1 = make_float4(acc[i][2].x + bias[4], acc[i][2].y + bias[5],
                                acc[i][3].x + bias[6], acc[i][3].y + bias[7]);
        *(float4*)(outbase + rowoff)     = o0;
        *(float4*)(outbase + rowoff + 4) = o1;
    }
}

// ==========================================================================
// Kernel 2: LSTM recurrence. 128 CTAs = (dir, batch). W_hh resident in smem
// as fp16. Layout: sW[p4][col] = uint4 holding half2 pairs for
// (gates 2col,2col+1) x (k = 4p4..4p4+3), arranged so half2->float2 converts
// feed FFMA2 directly (f32x2 lanes = even/odd k, reduced at loop exit).
// ==========================================================================
__global__ void __launch_bounds__(256) k_lstm(
    const float* __restrict__ Whf, const float* __restrict__ Whb)
{
    extern __shared__ __align__(16) char smem[];
    uint4* sW = (uint4*)smem;                       // 32*256*16 = 131072 B
    float* sh = (float*)(smem + 131072);            // h[128]
    float* sg = sh + 128;                           // gates[512]

    const int tid = threadIdx.x;
    const int dir = blockIdx.x >> 6;
    const int b   = blockIdx.x & 63;
    const float* Wh = dir ? Whb : Whf;

    for (int idx = tid; idx < 32 * 256; idx += 256) {
        int p4  = idx >> 8;
        int col = idx & 255;
        int g0  = col * 2;
        float4 w0 = *(const float4*)(Wh + (long)(g0    ) * 128 + p4 * 4);
        float4 w1 = *(const float4*)(Wh + (long)(g0 + 1) * 128 + p4 * 4);
        __half2 t0 = __floats2half2_rn(w0.x, w0.y);   // gate g0,  k even/odd
        __half2 t1 = __floats2half2_rn(w1.x, w1.y);   // gate g0+1
        __half2 t2 = __floats2half2_rn(w0.z, w0.w);
        __half2 t3 = __floats2half2_rn(w1.z, w1.w);
        uint4 u;
        u.x = *(unsigned*)&t0; u.y = *(unsigned*)&t1;
        u.z = *(unsigned*)&t2; u.w = *(unsigned*)&t3;
        sW[p4 * 256 + col] = u;
    }
    if (tid < 128) sh[tid] = 0.0f;
    float c = 0.0f;
    __syncthreads();

    const float* xwp = g_xw + (long)dir * BT_ * G4_ + (long)b * T_ * G4_;
    float* hout = g_h + (long)b * T_ * (2 * H_) + (dir ? H_ : 0);
    const float4* sh4 = (const float4*)sh;

    int t  = dir ? (T_ - 1) : 0;
    const int dt = dir ? -1 : 1;
    const int sec = tid >> 6;   // 0:i 1:f 2:g(tanh) 3:o

    for (int s = 0; s < T_; s++, t += dt) {
        float2 xv = *(const float2*)(xwp + (long)t * G4_ + 2 * tid);
        float2 accA = make_float2(xv.x, 0.0f);   // gate 2*tid   (even/odd k)
        float2 accB = make_float2(xv.y, 0.0f);   // gate 2*tid+1
#pragma unroll
        for (int p4 = 0; p4 < 32; p4++) {
            float4 h4 = sh4[p4];                 // broadcast LDS.128
            uint4  u  = sW[p4 * 256 + tid];      // LDS.128, conflict-free
            float2 h01 = make_float2(h4.x, h4.y);
            float2 h23 = make_float2(h4.z, h4.w);
            accA = ffma2(__half22float2(*(__half2*)&u.x), h01, accA);
            accB = ffma2(__half22float2(*(__half2*)&u.y), h01, accB);
            accA = ffma2(__half22float2(*(__half2*)&u.z), h23, accA);
            accB = ffma2(__half22float2(*(__half2*)&u.w), h23, accB);
        }
        float gA = accA.x + accA.y;
        float gB = accB.x + accB.y;
        if (sec == 2) { gA = fast_tanh(gA);    gB = fast_tanh(gB); }
        else          { gA = fast_sigmoid(gA); gB = fast_sigmoid(gB); }
        *(float2*)(sg + 2 * tid) = make_float2(gA, gB);
        __syncthreads();
        if (tid < 128) {
            float cc = fmaf(sg[128 + tid], c, sg[tid] * sg[256 + tid]);
            c = cc;
            float hv = sg[384 + tid] * fast_tanh(cc);
            sh[tid] = hv;
            hout[(long)t * (2 * H_) + tid] = hv;
        }
        __syncthreads();
    }
}

// ==========================================================================
// Kernel 3: logits = [h_f|h_b] @ fc_W^T + fc_b.   16 tokens / block.
// ==========================================================================
__global__ void __launch_bounds__(256) k_logits(
    const float* __restrict__ fcW, const float* __restrict__ fcb,
    float* __restrict__ logits)
{
    __shared__ float sW[20 * 257];
    __shared__ float shh[16 * 257];
    const int tid = threadIdx.x;
    const long bt0 = (long)blockIdx.x * 16;

    for (int i = tid; i < 20 * 256; i += 256) {
        int cc = i >> 8, k = i & 255;
        sW[cc * 257 + k] = fcW[i];
    }
    for (int i = tid; i < 16 * 256; i += 256) {
        int tk = i >> 8, k = i & 255;
        shh[tk * 257 + k] = g_h[(bt0 + tk) * 256 + k];
    }
    __syncthreads();
    for (int o = tid; o < 16 * 20; o += 256) {
        int tk = o / 20, cc = o % 20;
        float acc = fcb[cc];
        const float* hr = shh + tk * 257;
        const float* wr = sW  + cc * 257;
#pragma unroll 8
        for (int k = 0; k < 256; k++) acc = fmaf(hr[k], wr[k], acc);
        logits[(bt0 + tk) * C_ + cc] = acc;
    }
}

// ==========================================================================
// Kernel 4: CRF forward scan, one warp per batch.
// Key rewrite: E = exp(transitions) precomputed once; each step is
//   M = alpha[0]; ea = exp(alpha - M); s_j = dot(ea, E[:,j]);
//   alpha'[j] = emit[j] + M + log(s_j)
// => 1 exp + 1 log per lane per step (vs 20 exps before). Using alpha[0] as
// the stabilizer is safe: alpha spread is bounded by the emit-score spread
// (a few units), so exp stays in range and the sum has no cancellation.
// ==========================================================================
__global__ void k_crf(const float* __restrict__ logits,
                      const int*   __restrict__ tags,
                      const void*  __restrict__ maskp,
                      const float* __restrict__ trans)
{
    __shared__ float sT[400];          // raw transitions (for log_num)
    __shared__ float sEa[32];
    __shared__ float sAl[20];
    const int lane = threadIdx.x;
    const int b    = blockIdx.x;
    const int isbyte = (((const int*)maskp)[0] == 0x01010101);

    for (int i = lane; i < 400; i += 32) sT[i] = trans[i];
    __syncwarp();

    float Ecol[20];                    // E[i][lane] = exp(T[i][lane])
#pragma unroll
    for (int i = 0; i < 20; i++)
        Ecol[i] = (lane < 20) ? __expf(sT[i * 20 + lane]) : 0.0f;

    const float* lg  = logits + (long)b * T_ * C_;
    const long mbase = (long)b * T_;

    if (lane < 20) sAl[lane] = lg[lane];           // t = 0
    float em = (lane < 20) ? lg[C_ + lane] : 0.0f;
    sEa[lane] = 0.0f;
    __syncwarp();

    for (int t = 1; t < T_; t++) {
        float emN = (t + 1 < T_ && lane < 20) ? lg[(t + 1) * C_ + lane] : 0.0f;
        int   mt  = load_mask(maskp, mbase + t, isbyte);
        float a   = (lane < 20) ? sAl[lane] : 0.0f;
        float M   = sAl[0];                         // broadcast stabilizer
        if (lane < 20) sEa[lane] = __expf(a - M);
        __syncwarp();
        float s0 = 0.f, s1 = 0.f, s2 = 0.f, s3 = 0.f;
#pragma unroll
        for (int i = 0; i < 20; i += 4) {
            s0 = fmaf(sEa[i + 0], Ecol[i + 0], s0);
            s1 = fmaf(sEa[i + 1], Ecol[i + 1], s1);
            s2 = fmaf(sEa[i + 2], Ecol[i + 2], s2);
            s3 = fmaf(sEa[i + 3], Ecol[i + 3], s3);
        }
        float la   = em + M + __logf((s0 + s1) + (s2 + s3));
        float anew = mt ? la : a;
        __syncwarp();
        if (lane < 20) sAl[lane] = anew;
        __syncwarp();
        em = emN;
    }

    // log_den = logsumexp(final alpha)
    float v  = (lane < 20) ? sAl[lane] : -1e30f;
    float mx = v;
    for (int o = 16; o; o >>= 1) mx = fmaxf(mx, __shfl_xor_sync(0xffffffffu, mx, o));
    float e = (lane < 20) ? __expf(v - mx) : 0.0f;
    for (int o = 16; o; o >>= 1) e += __shfl_xor_sync(0xffffffffu, e, o);
    float log_den = mx + __logf(e);

    // log_num
    float sn = 0.0f;
    for (int t = lane; t < T_; t += 32) {
        int tg = tags[mbase + t];
        if (load_mask(maskp, mbase + t, isbyte)) sn += lg[t * C_ + tg];
    }
    for (int t = lane; t < T_ - 1; t += 32) {
        int a = tags[mbase + t], d = tags[mbase + t + 1];
        if (load_mask(maskp, mbase + t, isbyte) &
            load_mask(maskp, mbase + t + 1, isbyte))
            sn += sT[a * 20 + d];
    }
    for (int o = 16; o; o >>= 1) sn += __shfl_xor_sync(0xffffffffu, sn, o);
    if (lane == 0) g_res[b] = log_den - sn;
}

// Kernel 5: deterministic mean over batches -> loss
__global__ void k_final(float* __restrict__ out)
{
    const int lane = threadIdx.x;           // 32
    float v = g_res[lane] + g_res[lane + 32];
    for (int o = 16; o; o >>= 1) v += __shfl_xor_sync(0xffffffffu, v, o);
    if (lane == 0) out[0] = v * (1.0f / 64.0f);
}

// ==========================================================================
extern "C" void kernel_launch(void* const* d_in, const int* in_sizes, int n_in,
                              void* d_out, int out_size)
{
    const int*   x      = (const int*)  d_in[0];
    const void*  mask   =               d_in[1];
    const int*   tags   = (const int*)  d_in[2];
    const float* emb    = (const float*)d_in[3];
    const float* W_ih_f = (const float*)d_in[4];
    const float* W_hh_f = (const float*)d_in[5];
    const float* b_ih_f = (const float*)d_in[6];
    const float* b_hh_f = (const float*)d_in[7];
    const float* W_ih_b = (const float*)d_in[8];
    const float* W_hh_b = (const float*)d_in[9];
    const float* b_ih_b = (const float*)d_in[10];
    const float* b_hh_b = (const float*)d_in[11];
    const float* fc_W   = (const float*)d_in[12];
    const float* fc_b   = (const float*)d_in[13];
    const float* trans  = (const float*)d_in[14];

    float* out        = (float*)d_out;
    float* loss_ptr   = out;
    float* logits_ptr = out + 1;          // tuple order: (loss, logits)
    if (out_size == BT_ * C_) {           // logits-only layout fallback
        logits_ptr = out;
        loss_ptr   = nullptr;
    }

    const int lstm_smem = 131072 + 128 * 4 + 512 * 4;   // 133632 B
    cudaFuncSetAttribute(k_lstm, cudaFuncAttributeMaxDynamicSharedMemorySize,
                         lstm_smem);

    k_input_gemm<<<dim3(8, 256), 256>>>(x, emb, W_ih_f, W_ih_b,
                                        b_ih_f, b_hh_f, b_ih_b, b_hh_b);
    k_lstm<<<128, 256, lstm_smem>>>(W_hh_f, W_hh_b);
    k_logits<<<BT_ / 16, 256>>>(fc_W, fc_b, logits_ptr);
    k_crf<<<B_, 32>>>(logits_ptr, tags, mask, trans);
    if (loss_ptr) k_final<<<1, 32>>>(loss_ptr);
}

// round 3
// speedup vs baseline: 1.1942x; 1.0670x over previous
#include <cuda_runtime.h>
#include <cuda_fp16.h>
#include <cstdint>

#define B_   64
#define T_   512
#define H_   128
#define E_   300
#define C_   20
#define G4_  512
#define BT_  (B_ * T_)          // 32768

// -------- scratch (static device globals; no runtime allocation) -----------
__device__ __align__(16) float g_xw[2u * BT_ * G4_];   // 128 MB: [dir][bt][512]
__device__ __align__(16) float g_h [(unsigned)BT_ * 2 * H_];  // 32 MB
__device__ float g_res[B_];

// ----------------------------- math helpers --------------------------------
__device__ __forceinline__ float fast_sigmoid(float x) {
    return __fdividef(1.0f, 1.0f + __expf(-x));
}
__device__ __forceinline__ float fast_tanh(float x) {
    float ax = fabsf(x);
    float e  = __expf(-2.0f * ax);
    float t  = __fdividef(1.0f - e, 1.0f + e);
    return copysignf(t, x);
}
__device__ __forceinline__ int load_mask(const void* m, long idx, int isbyte) {
    return isbyte ? (int)((const unsigned char*)m)[idx] : ((const int*)m)[idx];
}
// Packed fp32x2 FMA (Blackwell): 2 fp32 FMAs per issue slot; PTX-only.
__device__ __forceinline__ float2 ffma2(float2 a, float2 b, float2 c) {
    unsigned long long ua = *reinterpret_cast<unsigned long long*>(&a);
    unsigned long long ub = *reinterpret_cast<unsigned long long*>(&b);
    unsigned long long uc = *reinterpret_cast<unsigned long long*>(&c);
    unsigned long long ud;
    asm("fma.rn.f32x2 %0, %1, %2, %3;" : "=l"(ud) : "l"(ua), "l"(ub), "l"(uc));
    return *reinterpret_cast<float2*>(&ud);
}

// ==========================================================================
// Kernel 1: fused embedding gather + input GEMM (both directions)
//   M=32768 (bt), N=1024 (dir*512+g), K=300.  BM=128 BN=128 BK=16, 8x8/thread
// ==========================================================================
__global__ void __launch_bounds__(256) k_input_gemm(
    const int*   __restrict__ x,
    const float* __restrict__ emb,
    const float* __restrict__ Wf,  const float* __restrict__ Wb,
    const float* __restrict__ bif, const float* __restrict__ bhf,
    const float* __restrict__ bib, const float* __restrict__ bhb)
{
    __shared__ __align__(16) float sA[16][128];
    __shared__ __align__(16) float sB[16][128];
    __shared__ int sIdx[128];

    const int tid   = threadIdx.x;
    const int m0    = blockIdx.y * 128;
    const int n0    = blockIdx.x * 128;
    const int dir   = n0 >> 9;
    const int gbase = n0 & 511;
    const float* W  = dir ? Wb : Wf;

    if (tid < 128) sIdx[tid] = x[m0 + tid];
    __syncthreads();

    float2 acc[8][4];
#pragma unroll
    for (int i = 0; i < 8; i++)
#pragma unroll
        for (int j = 0; j < 4; j++) acc[i][j] = make_float2(0.f, 0.f);

    const int tm0 = (tid >> 4) << 3;
    const int tn0 = (tid & 15) << 3;

    for (int ks = 0; ks < 19; ks++) {
        const int k0 = ks * 16;
        float4 va[2], vb[2];
#pragma unroll
        for (int r = 0; r < 2; r++) {
            int lid = tid * 2 + r;
            int row = lid >> 2;
            int q   = lid & 3;
            int kg  = k0 + 4 * q;
            if (kg < 300) {
                va[r] = *(const float4*)(emb + (long)sIdx[row] * 300 + kg);
                vb[r] = *(const float4*)(W   + (long)(gbase + row) * 300 + kg);
            } else {
                va[r] = make_float4(0.f, 0.f, 0.f, 0.f);
                vb[r] = make_float4(0.f, 0.f, 0.f, 0.f);
            }
        }
        __syncthreads();
#pragma unroll
        for (int r = 0; r < 2; r++) {
            int lid = tid * 2 + r;
            int row = lid >> 2;
            int q   = lid & 3;
            sA[4*q+0][row] = va[r].x; sA[4*q+1][row] = va[r].y;
            sA[4*q+2][row] = va[r].z; sA[4*q+3][row] = va[r].w;
            sB[4*q+0][row] = vb[r].x; sB[4*q+1][row] = vb[r].y;
            sB[4*q+2][row] = vb[r].z; sB[4*q+3][row] = vb[r].w;
        }
        __syncthreads();
#pragma unroll
        for (int kk = 0; kk < 16; kk++) {
            float a[8];
            float2 b2[4];
            *(float4*)(a)     = *(const float4*)&sA[kk][tm0];
            *(float4*)(a + 4) = *(const float4*)&sA[kk][tm0 + 4];
            *(float2*)(&b2[0]) = *(const float2*)&sB[kk][tn0];
            *(float2*)(&b2[1]) = *(const float2*)&sB[kk][tn0 + 2];
            *(float2*)(&b2[2]) = *(const float2*)&sB[kk][tn0 + 4];
            *(float2*)(&b2[3]) = *(const float2*)&sB[kk][tn0 + 6];
#pragma unroll
            for (int i = 0; i < 8; i++) {
                float2 ai = make_float2(a[i], a[i]);
#pragma unroll
                for (int j = 0; j < 4; j++)
                    acc[i][j] = ffma2(ai, b2[j], acc[i][j]);
            }
        }
    }

    const float* bi = dir ? bib : bif;
    const float* bh = dir ? bhb : bhf;
    float bias[8];
#pragma unroll
    for (int j = 0; j < 8; j++) {
        int g = gbase + tn0 + j;
        bias[j] = bi[g] + bh[g];
    }
    float* outbase = g_xw + (long)dir * BT_ * G4_;
#pragma unroll
    for (int i = 0; i < 8; i++) {
        long rowoff = (long)(m0 + tm0 + i) * G4_ + gbase + tn0;
        float4 o0 = make_float4(acc[i][0].x + bias[0], acc[i][0].y + bias[1],
                                acc[i][1].x + bias[2], acc[i][1].y + bias[3]);
        float4 o1 = make_float4(acc[i][2].x + bias[4], acc[i][2].y + bias[5],
                                acc[i][3].x + bias[6], acc[i][3].y + bias[7]);
        *(float4*)(outbase + rowoff)     = o0;
        *(float4*)(outbase + rowoff + 4) = o1;
    }
}

// ==========================================================================
// Kernel 2: LSTM recurrence. 128 CTAs = (dir, batch). W_hh resident in smem
// as fp16 (uint4 packed for FFMA2 consumption). The per-step xw load from
// DRAM-resident g_xw is software-prefetched one step ahead so its ~600-cycle
// latency hides behind the matvec instead of stalling every step.
// ==========================================================================
__global__ void __launch_bounds__(256) k_lstm(
    const float* __restrict__ Whf, const float* __restrict__ Whb)
{
    extern __shared__ __align__(16) char smem[];
    uint4* sW = (uint4*)smem;                       // 32*256*16 = 131072 B
    float* sh = (float*)(smem + 131072);            // h[128]
    float* sg = sh + 128;                           // gates[512]

    const int tid = threadIdx.x;
    const int dir = blockIdx.x >> 6;
    const int b   = blockIdx.x & 63;
    const float* Wh = dir ? Whb : Whf;

    for (int idx = tid; idx < 32 * 256; idx += 256) {
        int p4  = idx >> 8;
        int col = idx & 255;
        int g0  = col * 2;
        float4 w0 = *(const float4*)(Wh + (long)(g0    ) * 128 + p4 * 4);
        float4 w1 = *(const float4*)(Wh + (long)(g0 + 1) * 128 + p4 * 4);
        __half2 t0 = __floats2half2_rn(w0.x, w0.y);
        __half2 t1 = __floats2half2_rn(w1.x, w1.y);
        __half2 t2 = __floats2half2_rn(w0.z, w0.w);
        __half2 t3 = __floats2half2_rn(w1.z, w1.w);
        uint4 u;
        u.x = *(unsigned*)&t0; u.y = *(unsigned*)&t1;
        u.z = *(unsigned*)&t2; u.w = *(unsigned*)&t3;
        sW[p4 * 256 + col] = u;
    }
    if (tid < 128) sh[tid] = 0.0f;
    float c = 0.0f;
    __syncthreads();

    const float* xwp = g_xw + (long)dir * BT_ * G4_ + (long)b * T_ * G4_;
    float* hout = g_h + (long)b * T_ * (2 * H_) + (dir ? H_ : 0);
    const float4* sh4 = (const float4*)sh;

    int t  = dir ? (T_ - 1) : 0;
    const int dt = dir ? -1 : 1;
    const int sec = tid >> 6;   // 0:i 1:f 2:g(tanh) 3:o

    float2 xv_next = *(const float2*)(xwp + (long)t * G4_ + 2 * tid);

    for (int s = 0; s < T_; s++, t += dt) {
        float2 xv = xv_next;
        if (s + 1 < T_)     // prefetch next step's xw; consumed next iteration
            xv_next = *(const float2*)(xwp + (long)(t + dt) * G4_ + 2 * tid);

        float2 accA = make_float2(xv.x, 0.0f);
        float2 accB = make_float2(xv.y, 0.0f);
#pragma unroll
        for (int p4 = 0; p4 < 32; p4++) {
            float4 h4 = sh4[p4];
            uint4  u  = sW[p4 * 256 + tid];
            float2 h01 = make_float2(h4.x, h4.y);
            float2 h23 = make_float2(h4.z, h4.w);
            accA = ffma2(__half22float2(*(__half2*)&u.x), h01, accA);
            accB = ffma2(__half22float2(*(__half2*)&u.y), h01, accB);
            accA = ffma2(__half22float2(*(__half2*)&u.z), h23, accA);
            accB = ffma2(__half22float2(*(__half2*)&u.w), h23, accB);
        }
        float gA = accA.x + accA.y;
        float gB = accB.x + accB.y;
        if (sec == 2) { gA = fast_tanh(gA);    gB = fast_tanh(gB); }
        else          { gA = fast_sigmoid(gA); gB = fast_sigmoid(gB); }
        *(float2*)(sg + 2 * tid) = make_float2(gA, gB);
        __syncthreads();
        if (tid < 128) {
            float cc = fmaf(sg[128 + tid], c, sg[tid] * sg[256 + tid]);
            c = cc;
            float hv = sg[384 + tid] * fast_tanh(cc);
            sh[tid] = hv;
            hout[(long)t * (2 * H_) + tid] = hv;
        }
        __syncthreads();
    }
}

// ==========================================================================
// Kernel 3: logits = [h_f|h_b] @ fc_W^T + fc_b.   16 tokens / block.
// ==========================================================================
__global__ void __launch_bounds__(256) k_logits(
    const float* __restrict__ fcW, const float* __restrict__ fcb,
    float* __restrict__ logits)
{
    __shared__ float sW[20 * 257];
    __shared__ float shh[16 * 257];
    const int tid = threadIdx.x;
    const long bt0 = (long)blockIdx.x * 16;

    for (int i = tid; i < 20 * 256; i += 256) {
        int cc = i >> 8, k = i & 255;
        sW[cc * 257 + k] = fcW[i];
    }
    for (int i = tid; i < 16 * 256; i += 256) {
        int tk = i >> 8, k = i & 255;
        shh[tk * 257 + k] = g_h[(bt0 + tk) * 256 + k];
    }
    __syncthreads();
    for (int o = tid; o < 16 * 20; o += 256) {
        int tk = o / 20, cc = o % 20;
        const float* hr = shh + tk * 257;
        const float* wr = sW  + cc * 257;
        float a0 = 0.f, a1 = 0.f, a2 = 0.f, a3 = 0.f;
#pragma unroll 16
        for (int k = 0; k < 256; k += 4) {
            a0 = fmaf(hr[k + 0], wr[k + 0], a0);
            a1 = fmaf(hr[k + 1], wr[k + 1], a1);
            a2 = fmaf(hr[k + 2], wr[k + 2], a2);
            a3 = fmaf(hr[k + 3], wr[k + 3], a3);
        }
        logits[(bt0 + tk) * C_ + cc] = fcb[cc] + ((a0 + a1) + (a2 + a3));
    }
}

// ==========================================================================
// Kernel 4: CRF forward scan — register/shfl dataflow, one warp per batch.
//   alpha lives in a register per lane (lane<20). Per step:
//     M = shfl(alpha,0); ea = exp(alpha-M); s_j = sum_i shfl(ea,i)*E[i][j]
//     alpha_j = emit_j + M + log(s_j)
//   Mask is loaded once per 32 steps (one LDG per lane) and extracted per
//   step via shfl. Emit row is prefetched one step ahead. No smem, no
//   syncwarp in the hot loop.
// ==========================================================================
__global__ void k_crf(const float* __restrict__ logits,
                      const int*   __restrict__ tags,
                      const void*  __restrict__ maskp,
                      const float* __restrict__ trans)
{
    __shared__ float sT[400];          // raw transitions (for log_num)
    const int lane = threadIdx.x;
    const int b    = blockIdx.x;
    const int isbyte = (((const int*)maskp)[0] == 0x01010101);

    for (int i = lane; i < 400; i += 32) sT[i] = trans[i];
    __syncwarp();

    float Ecol[20];                    // E[i][lane] = exp(T[i][lane])
#pragma unroll
    for (int i = 0; i < 20; i++)
        Ecol[i] = (lane < 20) ? __expf(sT[i * 20 + lane]) : 0.0f;

    const float* lg  = logits + (long)b * T_ * C_;
    const long mbase = (long)b * T_;

    float a  = (lane < 20) ? lg[lane]      : 0.0f;   // alpha at t=0
    float em = (lane < 20) ? lg[C_ + lane] : 0.0f;   // emit for t=1

    for (int tb = 0; tb < T_; tb += 32) {
        int mv = load_mask(maskp, mbase + tb + lane, isbyte);
        const int tlo = (tb == 0) ? 1 : tb;
        for (int t = tlo; t < tb + 32; t++) {
            float emN = (t + 1 < T_ && lane < 20) ? lg[(t + 1) * C_ + lane]
                                                  : 0.0f;
            int   mt  = __shfl_sync(0xffffffffu, mv, t - tb);
            float M   = __shfl_sync(0xffffffffu, a, 0);
            float ea  = __expf(a - M);
            float s0 = 0.f, s1 = 0.f, s2 = 0.f, s3 = 0.f;
#pragma unroll
            for (int i = 0; i < 20; i += 4) {
                s0 = fmaf(__shfl_sync(0xffffffffu, ea, i + 0), Ecol[i + 0], s0);
                s1 = fmaf(__shfl_sync(0xffffffffu, ea, i + 1), Ecol[i + 1], s1);
                s2 = fmaf(__shfl_sync(0xffffffffu, ea, i + 2), Ecol[i + 2], s2);
                s3 = fmaf(__shfl_sync(0xffffffffu, ea, i + 3), Ecol[i + 3], s3);
            }
            float la = em + M + __logf((s0 + s1) + (s2 + s3));
            a  = mt ? la : a;
            em = emN;
        }
    }

    // log_den = logsumexp(final alpha)
    float v  = (lane < 20) ? a : -1e30f;
    float mx = v;
    for (int o = 16; o; o >>= 1) mx = fmaxf(mx, __shfl_xor_sync(0xffffffffu, mx, o));
    float e = (lane < 20) ? __expf(v - mx) : 0.0f;
    for (int o = 16; o; o >>= 1) e += __shfl_xor_sync(0xffffffffu, e, o);
    float log_den = mx + __logf(e);

    // log_num
    float sn = 0.0f;
    for (int t = lane; t < T_; t += 32) {
        int tg = tags[mbase + t];
        if (load_mask(maskp, mbase + t, isbyte)) sn += lg[t * C_ + tg];
    }
    for (int t = lane; t < T_ - 1; t += 32) {
        int aa = tags[mbase + t], d = tags[mbase + t + 1];
        if (load_mask(maskp, mbase + t, isbyte) &
            load_mask(maskp, mbase + t + 1, isbyte))
            sn += sT[aa * 20 + d];
    }
    for (int o = 16; o; o >>= 1) sn += __shfl_xor_sync(0xffffffffu, sn, o);
    if (lane == 0) g_res[b] = log_den - sn;
}

// Kernel 5: deterministic mean over batches -> loss
__global__ void k_final(float* __restrict__ out)
{
    const int lane = threadIdx.x;           // 32
    float v = g_res[lane] + g_res[lane + 32];
    for (int o = 16; o; o >>= 1) v += __shfl_xor_sync(0xffffffffu, v, o);
    if (lane == 0) out[0] = v * (1.0f / 64.0f);
}

// ==========================================================================
extern "C" void kernel_launch(void* const* d_in, const int* in_sizes, int n_in,
                              void* d_out, int out_size)
{
    const int*   x      = (const int*)  d_in[0];
    const void*  mask   =               d_in[1];
    const int*   tags   = (const int*)  d_in[2];
    const float* emb    = (const float*)d_in[3];
    const float* W_ih_f = (const float*)d_in[4];
    const float* W_hh_f = (const float*)d_in[5];
    const float* b_ih_f = (const float*)d_in[6];
    const float* b_hh_f = (const float*)d_in[7];
    const float* W_ih_b = (const float*)d_in[8];
    const float* W_hh_b = (const float*)d_in[9];
    const float* b_ih_b = (const float*)d_in[10];
    const float* b_hh_b = (const float*)d_in[11];
    const float* fc_W   = (const float*)d_in[12];
    const float* fc_b   = (const float*)d_in[13];
    const float* trans  = (const float*)d_in[14];

    float* out        = (float*)d_out;
    float* loss_ptr   = out;
    float* logits_ptr = out + 1;          // tuple order: (loss, logits)
    if (out_size == BT_ * C_) {           // logits-only layout fallback
        logits_ptr = out;
        loss_ptr   = nullptr;
    }

    const int lstm_smem = 131072 + 128 * 4 + 512 * 4;   // 133632 B
    cudaFuncSetAttribute(k_lstm, cudaFuncAttributeMaxDynamicSharedMemorySize,
                         lstm_smem);

    k_input_gemm<<<dim3(8, 256), 256>>>(x, emb, W_ih_f, W_ih_b,
                                        b_ih_f, b_hh_f, b_ih_b, b_hh_b);
    k_lstm<<<128, 256, lstm_smem>>>(W_hh_f, W_hh_b);
    k_logits<<<BT_ / 16, 256>>>(fc_W, fc_b, logits_ptr);
    k_crf<<<B_, 32>>>(logits_ptr, tags, mask, trans);
    if (loss_ptr) k_final<<<1, 32>>>(loss_ptr);
}

// round 4
// speedup vs baseline: 1.2251x; 1.0258x over previous
#include <cuda_runtime.h>
#include <cuda_fp16.h>
#include <cstdint>

#define B_   64
#define T_   512
#define H_   128
#define E_   300
#define C_   20
#define G4_  512
#define BT_  (B_ * T_)          // 32768

// -------- scratch (static device globals; no runtime allocation) -----------
__device__ __align__(16) float g_xw[2u * BT_ * G4_];   // 128 MB
__device__ __align__(16) float g_h [(unsigned)BT_ * 2 * H_];  // 32 MB
__device__ __align__(16) float g_eexp[(unsigned)BT_ * C_];    // exp(em_j - em_0)
__device__ float g_em0[BT_];                                   // em_0 per token
__device__ float g_res[B_];

// ----------------------------- math helpers --------------------------------
__device__ __forceinline__ float fast_sigmoid(float x) {
    return __fdividef(1.0f, 1.0f + __expf(-x));
}
__device__ __forceinline__ float fast_tanh(float x) {
    float ax = fabsf(x);
    float e  = __expf(-2.0f * ax);
    float t  = __fdividef(1.0f - e, 1.0f + e);
    return copysignf(t, x);
}
__device__ __forceinline__ int load_mask(const void* m, long idx, int isbyte) {
    return isbyte ? (int)((const unsigned char*)m)[idx] : ((const int*)m)[idx];
}
__device__ __forceinline__ float2 ffma2(float2 a, float2 b, float2 c) {
    unsigned long long ua = *reinterpret_cast<unsigned long long*>(&a);
    unsigned long long ub = *reinterpret_cast<unsigned long long*>(&b);
    unsigned long long uc = *reinterpret_cast<unsigned long long*>(&c);
    unsigned long long ud;
    asm("fma.rn.f32x2 %0, %1, %2, %3;" : "=l"(ud) : "l"(ua), "l"(ub), "l"(uc));
    return *reinterpret_cast<float2*>(&ud);
}

// ==========================================================================
// Kernel 1: fused embedding gather + input GEMM, register double-buffered.
//   BM=128 BN=128 BK=16, 8x8/thread. LDG for slice ks+1 issued before the
//   compute phase of slice ks so the gather latency hides under FFMA2 work.
// ==========================================================================
__global__ void __launch_bounds__(256, 2) k_input_gemm(
    const int*   __restrict__ x,
    const float* __restrict__ emb,
    const float* __restrict__ Wf,  const float* __restrict__ Wb,
    const float* __restrict__ bif, const float* __restrict__ bhf,
    const float* __restrict__ bib, const float* __restrict__ bhb)
{
    __shared__ __align__(16) float sA[16][128];
    __shared__ __align__(16) float sB[16][128];
    __shared__ int sIdx[128];

    const int tid   = threadIdx.x;
    const int m0    = blockIdx.y * 128;
    const int n0    = blockIdx.x * 128;
    const int dir   = n0 >> 9;
    const int gbase = n0 & 511;
    const float* W  = dir ? Wb : Wf;

    if (tid < 128) sIdx[tid] = x[m0 + tid];
    __syncthreads();

    // per-thread load coordinates (2 rows of 4 floats in A and B each)
    const int row0 = (tid * 2)     >> 2, q0 = (tid * 2)     & 3;
    const int row1 = (tid * 2 + 1) >> 2, q1 = (tid * 2 + 1) & 3;
    const long arow0 = (long)sIdx[row0] * 300, arow1 = (long)sIdx[row1] * 300;
    const long brow0 = (long)(gbase + row0) * 300, brow1 = (long)(gbase + row1) * 300;

    float2 acc[8][4];
#pragma unroll
    for (int i = 0; i < 8; i++)
#pragma unroll
        for (int j = 0; j < 4; j++) acc[i][j] = make_float2(0.f, 0.f);

    const int tm0 = (tid >> 4) << 3;
    const int tn0 = (tid & 15) << 3;

    float4 va0, va1, vb0, vb1;          // current slice registers
    {   // prologue: load slice 0
        int kg0 = 4 * q0, kg1 = 4 * q1;
        va0 = *(const float4*)(emb + arow0 + kg0);
        vb0 = *(const float4*)(W   + brow0 + kg0);
        va1 = *(const float4*)(emb + arow1 + kg1);
        vb1 = *(const float4*)(W   + brow1 + kg1);
    }

    for (int ks = 0; ks < 19; ks++) {
        // stage current slice into smem
        sA[4*q0+0][row0] = va0.x; sA[4*q0+1][row0] = va0.y;
        sA[4*q0+2][row0] = va0.z; sA[4*q0+3][row0] = va0.w;
        sB[4*q0+0][row0] = vb0.x; sB[4*q0+1][row0] = vb0.y;
        sB[4*q0+2][row0] = vb0.z; sB[4*q0+3][row0] = vb0.w;
        sA[4*q1+0][row1] = va1.x; sA[4*q1+1][row1] = va1.y;
        sA[4*q1+2][row1] = va1.z; sA[4*q1+3][row1] = va1.w;
        sB[4*q1+0][row1] = vb1.x; sB[4*q1+1][row1] = vb1.y;
        sB[4*q1+2][row1] = vb1.z; sB[4*q1+3][row1] = vb1.w;
        __syncthreads();

        // issue next slice's loads NOW; latency hides under compute below
        if (ks < 18) {
            int k0  = (ks + 1) * 16;
            int kg0 = k0 + 4 * q0, kg1 = k0 + 4 * q1;
            if (kg0 < 300) {
                va0 = *(const float4*)(emb + arow0 + kg0);
                vb0 = *(const float4*)(W   + brow0 + kg0);
            } else { va0 = make_float4(0,0,0,0); vb0 = make_float4(0,0,0,0); }
            if (kg1 < 300) {
                va1 = *(const float4*)(emb + arow1 + kg1);
                vb1 = *(const float4*)(W   + brow1 + kg1);
            } else { va1 = make_float4(0,0,0,0); vb1 = make_float4(0,0,0,0); }
        }

#pragma unroll
        for (int kk = 0; kk < 16; kk++) {
            float a[8];
            float2 b2[4];
            *(float4*)(a)     = *(const float4*)&sA[kk][tm0];
            *(float4*)(a + 4) = *(const float4*)&sA[kk][tm0 + 4];
            *(float2*)(&b2[0]) = *(const float2*)&sB[kk][tn0];
            *(float2*)(&b2[1]) = *(const float2*)&sB[kk][tn0 + 2];
            *(float2*)(&b2[2]) = *(const float2*)&sB[kk][tn0 + 4];
            *(float2*)(&b2[3]) = *(const float2*)&sB[kk][tn0 + 6];
#pragma unroll
            for (int i = 0; i < 8; i++) {
                float2 ai = make_float2(a[i], a[i]);
#pragma unroll
                for (int j = 0; j < 4; j++)
                    acc[i][j] = ffma2(ai, b2[j], acc[i][j]);
            }
        }
        __syncthreads();
    }

    const float* bi = dir ? bib : bif;
    const float* bh = dir ? bhb : bhf;
    float bias[8];
#pragma unroll
    for (int j = 0; j < 8; j++) {
        int g = gbase + tn0 + j;
        bias[j] = bi[g] + bh[g];
    }
    float* outbase = g_xw + (long)dir * BT_ * G4_;
#pragma unroll
    for (int i = 0; i < 8; i++) {
        long rowoff = (long)(m0 + tm0 + i) * G4_ + gbase + tn0;
        float4 o0 = make_float4(acc[i][0].x + bias[0], acc[i][0].y + bias[1],
                                acc[i][1].x + bias[2], acc[i][1].y + bias[3]);
        float4 o1 = make_float4(acc[i][2].x + bias[4], acc[i][2].y + bias[5],
                                acc[i][3].x + bias[6], acc[i][3].y + bias[7]);
        *(float4*)(outbase + rowoff)     = o0;
        *(float4*)(outbase + rowoff + 4) = o1;
    }
}

// ==========================================================================
// Kernel 2: LSTM recurrence (unchanged from R3: smem fp16 W + xw prefetch).
// ==========================================================================
__global__ void __launch_bounds__(256) k_lstm(
    const float* __restrict__ Whf, const float* __restrict__ Whb)
{
    extern __shared__ __align__(16) char smem[];
    uint4* sW = (uint4*)smem;                       // 131072 B
    float* sh = (float*)(smem + 131072);
    float* sg = sh + 128;

    const int tid = threadIdx.x;
    const int dir = blockIdx.x >> 6;
    const int b   = blockIdx.x & 63;
    const float* Wh = dir ? Whb : Whf;

    for (int idx = tid; idx < 32 * 256; idx += 256) {
        int p4  = idx >> 8;
        int col = idx & 255;
        int g0  = col * 2;
        float4 w0 = *(const float4*)(Wh + (long)(g0    ) * 128 + p4 * 4);
        float4 w1 = *(const float4*)(Wh + (long)(g0 + 1) * 128 + p4 * 4);
        __half2 t0 = __floats2half2_rn(w0.x, w0.y);
        __half2 t1 = __floats2half2_rn(w1.x, w1.y);
        __half2 t2 = __floats2half2_rn(w0.z, w0.w);
        __half2 t3 = __floats2half2_rn(w1.z, w1.w);
        uint4 u;
        u.x = *(unsigned*)&t0; u.y = *(unsigned*)&t1;
        u.z = *(unsigned*)&t2; u.w = *(unsigned*)&t3;
        sW[p4 * 256 + col] = u;
    }
    if (tid < 128) sh[tid] = 0.0f;
    float c = 0.0f;
    __syncthreads();

    const float* xwp = g_xw + (long)dir * BT_ * G4_ + (long)b * T_ * G4_;
    float* hout = g_h + (long)b * T_ * (2 * H_) + (dir ? H_ : 0);
    const float4* sh4 = (const float4*)sh;

    int t  = dir ? (T_ - 1) : 0;
    const int dt = dir ? -1 : 1;
    const int sec = tid >> 6;

    float2 xv_next = *(const float2*)(xwp + (long)t * G4_ + 2 * tid);

    for (int s = 0; s < T_; s++, t += dt) {
        float2 xv = xv_next;
        if (s + 1 < T_)
            xv_next = *(const float2*)(xwp + (long)(t + dt) * G4_ + 2 * tid);

        float2 accA = make_float2(xv.x, 0.0f);
        float2 accB = make_float2(xv.y, 0.0f);
#pragma unroll
        for (int p4 = 0; p4 < 32; p4++) {
            float4 h4 = sh4[p4];
            uint4  u  = sW[p4 * 256 + tid];
            float2 h01 = make_float2(h4.x, h4.y);
            float2 h23 = make_float2(h4.z, h4.w);
            accA = ffma2(__half22float2(*(__half2*)&u.x), h01, accA);
            accB = ffma2(__half22float2(*(__half2*)&u.y), h01, accB);
            accA = ffma2(__half22float2(*(__half2*)&u.z), h23, accA);
            accB = ffma2(__half22float2(*(__half2*)&u.w), h23, accB);
        }
        float gA = accA.x + accA.y;
        float gB = accB.x + accB.y;
        if (sec == 2) { gA = fast_tanh(gA);    gB = fast_tanh(gB); }
        else          { gA = fast_sigmoid(gA); gB = fast_sigmoid(gB); }
        *(float2*)(sg + 2 * tid) = make_float2(gA, gB);
        __syncthreads();
        if (tid < 128) {
            float cc = fmaf(sg[128 + tid], c, sg[tid] * sg[256 + tid]);
            c = cc;
            float hv = sg[384 + tid] * fast_tanh(cc);
            sh[tid] = hv;
            hout[(long)t * (2 * H_) + tid] = hv;
        }
        __syncthreads();
    }
}

// ==========================================================================
// Kernel 3: logits + CRF emission precompute.
//   Also writes g_eexp[bt][j] = exp(logit_j - logit_0), g_em0[bt] = logit_0.
// ==========================================================================
__global__ void __launch_bounds__(256) k_logits(
    const float* __restrict__ fcW, const float* __restrict__ fcb,
    float* __restrict__ logits)
{
    __shared__ float sW[20 * 257];
    __shared__ float shh[16 * 257];
    __shared__ float sl[16 * 20];
    const int tid = threadIdx.x;
    const long bt0 = (long)blockIdx.x * 16;

    for (int i = tid; i < 20 * 256; i += 256) {
        int cc = i >> 8, k = i & 255;
        sW[cc * 257 + k] = fcW[i];
    }
    for (int i = tid; i < 16 * 256; i += 256) {
        int tk = i >> 8, k = i & 255;
        shh[tk * 257 + k] = g_h[(bt0 + tk) * 256 + k];
    }
    __syncthreads();
    for (int o = tid; o < 16 * 20; o += 256) {
        int tk = o / 20, cc = o % 20;
        const float* hr = shh + tk * 257;
        const float* wr = sW  + cc * 257;
        float a0 = 0.f, a1 = 0.f, a2 = 0.f, a3 = 0.f;
#pragma unroll 16
        for (int k = 0; k < 256; k += 4) {
            a0 = fmaf(hr[k + 0], wr[k + 0], a0);
            a1 = fmaf(hr[k + 1], wr[k + 1], a1);
            a2 = fmaf(hr[k + 2], wr[k + 2], a2);
            a3 = fmaf(hr[k + 3], wr[k + 3], a3);
        }
        float lv = fcb[cc] + ((a0 + a1) + (a2 + a3));
        sl[o] = lv;
        logits[(bt0 + tk) * C_ + cc] = lv;
    }
    __syncthreads();
    for (int o = tid; o < 16 * 20; o += 256) {
        int tk = o / 20, cc = o % 20;
        g_eexp[(bt0 + tk) * C_ + cc] = __expf(sl[o] - sl[tk * 20]);
        if (cc == 0) g_em0[bt0 + tk] = sl[tk * 20];
    }
}

// ==========================================================================
// Kernel 4: CRF forward scan — exp-space recurrence, zero MUFU in hot loop.
//   alpha = L + log(u).  Per step: s_j = sum_i u_i E_ij (shfl broadcast),
//   u'_j = eexp_t[j]*s_j, L += em0_t.  Rescale every 4 steps. Mask is a
//   monotone prefix => loop runs exactly len steps, unmasked.
// ==========================================================================
__global__ void k_crf(const float* __restrict__ logits,
                      const int*   __restrict__ tags,
                      const void*  __restrict__ maskp,
                      const float* __restrict__ trans)
{
    __shared__ float sT[400];
    const int lane = threadIdx.x;
    const int b    = blockIdx.x;
    const int isbyte = (((const int*)maskp)[0] == 0x01010101);

    for (int i = lane; i < 400; i += 32) sT[i] = trans[i];
    __syncwarp();

    float Ecol[20];
#pragma unroll
    for (int i = 0; i < 20; i++)
        Ecol[i] = (lane < 20) ? __expf(sT[i * 20 + lane]) : 0.0f;

    const long mbase = (long)b * T_;
    // sequence length (mask is a monotone prefix)
    int len = 0;
    for (int t = lane; t < T_; t += 32)
        len += (load_mask(maskp, mbase + t, isbyte) != 0);
    for (int o = 16; o; o >>= 1) len += __shfl_xor_sync(0xffffffffu, len, o);

    const float* ee  = g_eexp + mbase * C_;
    const float* em0 = g_em0 + mbase;
    const float* lg  = logits + mbase * C_;

    float u = (lane < 20) ? ee[lane] : 0.0f;   // t = 0
    float L = em0[0];

    float eeN  = (lane < 20 && 1 < len) ? ee[C_ + lane] : 0.0f;
    float em0N = (1 < len) ? em0[1] : 0.0f;

    for (int t = 1; t < len; t++) {
        float eeC = eeN, em0C = em0N;
        if (t + 1 < len) {                      // prefetch next row
            eeN  = (lane < 20) ? ee[(t + 1) * C_ + lane] : 0.0f;
            em0N = em0[t + 1];
        }
        float s0 = 0.f, s1 = 0.f, s2 = 0.f, s3 = 0.f;
#pragma unroll
        for (int i = 0; i < 20; i += 4) {
            s0 = fmaf(__shfl_sync(0xffffffffu, u, i + 0), Ecol[i + 0], s0);
            s1 = fmaf(__shfl_sync(0xffffffffu, u, i + 1), Ecol[i + 1], s1);
            s2 = fmaf(__shfl_sync(0xffffffffu, u, i + 2), Ecol[i + 2], s2);
            s3 = fmaf(__shfl_sync(0xffffffffu, u, i + 3), Ecol[i + 3], s3);
        }
        u = eeC * ((s0 + s1) + (s2 + s3));
        L += em0C;
        if ((t & 3) == 0) {                     // rescale; log off the chain
            float k = __shfl_sync(0xffffffffu, u, 0);
            u *= __fdividef(1.0f, k);
            L += __logf(k);
        }
    }

    // log_den = L + log(sum_j u_j)
    float e = u;
    for (int o = 16; o; o >>= 1) e += __shfl_xor_sync(0xffffffffu, e, o);
    float log_den = L + __logf(e);

    // log_num (only t < len contributes; mask is a prefix)
    float sn = 0.0f;
    for (int t = lane; t < len; t += 32)
        sn += lg[t * C_ + tags[mbase + t]];
    for (int t = lane; t < len - 1; t += 32)
        sn += sT[tags[mbase + t] * 20 + tags[mbase + t + 1]];
    for (int o = 16; o; o >>= 1) sn += __shfl_xor_sync(0xffffffffu, sn, o);
    if (lane == 0) g_res[b] = log_den - sn;
}

// Kernel 5: deterministic mean over batches -> loss
__global__ void k_final(float* __restrict__ out)
{
    const int lane = threadIdx.x;
    float v = g_res[lane] + g_res[lane + 32];
    for (int o = 16; o; o >>= 1) v += __shfl_xor_sync(0xffffffffu, v, o);
    if (lane == 0) out[0] = v * (1.0f / 64.0f);
}

// ==========================================================================
extern "C" void kernel_launch(void* const* d_in, const int* in_sizes, int n_in,
                              void* d_out, int out_size)
{
    const int*   x      = (const int*)  d_in[0];
    const void*  mask   =               d_in[1];
    const int*   tags   = (const int*)  d_in[2];
    const float* emb    = (const float*)d_in[3];
    const float* W_ih_f = (const float*)d_in[4];
    const float* W_hh_f = (const float*)d_in[5];
    const float* b_ih_f = (const float*)d_in[6];
    const float* b_hh_f = (const float*)d_in[7];
    const float* W_ih_b = (const float*)d_in[8];
    const float* W_hh_b = (const float*)d_in[9];
    const float* b_ih_b = (const float*)d_in[10];
    const float* b_hh_b = (const float*)d_in[11];
    const float* fc_W   = (const float*)d_in[12];
    const float* fc_b   = (const float*)d_in[13];
    const float* trans  = (const float*)d_in[14];

    float* out        = (float*)d_out;
    float* loss_ptr   = out;
    float* logits_ptr = out + 1;
    if (out_size == BT_ * C_) {
        logits_ptr = out;
        loss_ptr   = nullptr;
    }

    const int lstm_smem = 131072 + 128 * 4 + 512 * 4;
    cudaFuncSetAttribute(k_lstm, cudaFuncAttributeMaxDynamicSharedMemorySize,
                         lstm_smem);

    k_input_gemm<<<dim3(8, 256), 256>>>(x, emb, W_ih_f, W_ih_b,
                                        b_ih_f, b_hh_f, b_ih_b, b_hh_b);
    k_lstm<<<128, 256, lstm_smem>>>(W_hh_f, W_hh_b);
    k_logits<<<BT_ / 16, 256>>>(fc_W, fc_b, logits_ptr);
    k_crf<<<B_, 32>>>(logits_ptr, tags, mask, trans);
    if (loss_ptr) k_final<<<1, 32>>>(loss_ptr);
}